// round 3
// baseline (speedup 1.0000x reference)
#include <cuda_runtime.h>
#include <cuda_fp16.h>
#include <cstdint>

// ============================================================================
// QuantizedLinear: out[8192,4096] = x[8192,4096] @ dequant(W4)[4096,4096]^T + bias
// mma.sync fp16 GEMM (compute_103-safe: no tcgen05 / no "a" features).
// Operands pre-converted + pre-tiled + SW128-pre-swizzled into __device__ scratch,
// streamed into smem with cp.async.bulk + mbarrier pipeline, read via ldmatrix.
// ============================================================================

#define M_TOTAL   8192
#define N_TOTAL   4096
#define K_TOTAL   4096
#define BK        64            // k per stage (64 halves = 128B rows)
#define STAGES    4
#define K_ITERS   (K_TOTAL / BK)   // 64
#define TM        128
#define TN        256

// g_A: [m_blk(64)][k_stage(64)] blocks of 128x64 fp16 (16KB), SW128-swizzled
// g_W: [n_blk(16)][k_stage(64)] blocks of 256x64 fp16 (32KB), SW128-swizzled
__device__ __align__(1024) __half g_A[33554432];  // 64 MiB
__device__ __align__(1024) __half g_W[16777216];  // 32 MiB

__device__ __forceinline__ uint32_t swz(uint32_t x) { return x ^ ((x >> 3) & 0x70); }

__device__ __forceinline__ uint32_t smem_u32(const void* p) {
    uint32_t a;
    asm("{ .reg .u64 t; cvta.to.shared.u64 t, %1; cvt.u32.u64 %0, t; }" : "=r"(a) : "l"(p));
    return a;
}

#define MBARRIER_INIT(addr, cnt) \
    asm volatile("mbarrier.init.shared.b64 [%0], %1;" :: "r"((uint32_t)(addr)), "r"((uint32_t)(cnt)) : "memory")

#define MBARRIER_EXPECT_TX(addr, bytes) \
    asm volatile("mbarrier.arrive.expect_tx.shared.b64 _, [%0], %1;" :: "r"((uint32_t)(addr)), "r"((uint32_t)(bytes)) : "memory")

#define MBARRIER_ARRIVE(addr) \
    asm volatile("mbarrier.arrive.shared.b64 _, [%0];" :: "r"((uint32_t)(addr)) : "memory")

#define MBARRIER_WAIT_PARITY(addr, par) do {                                            \
    uint32_t _m = (uint32_t)(addr), _p = (uint32_t)(par), _d;                           \
    asm volatile("{\n\t.reg .pred p;\n\t"                                               \
        "mbarrier.try_wait.parity.acquire.cta.shared::cta.b64 p, [%1], %2;\n\t"         \
        "selp.b32 %0, 1, 0, p;\n\t}" : "=r"(_d) : "r"(_m), "r"(_p) : "memory");         \
    if (!_d) {                                                                          \
        asm volatile("{\n\t.reg .pred P1;\n\t"                                          \
            "WL_%=:\n\t"                                                                \
            "mbarrier.try_wait.parity.acquire.cta.shared::cta.b64 P1, [%0], %1, 0x989680;\n\t" \
            "@P1 bra.uni WD_%=;\n\tbra.uni WL_%=;\n\tWD_%=:\n\t}"                       \
            :: "r"(_m), "r"(_p) : "memory");                                            \
    }                                                                                   \
} while (0)

#define MBARRIER_WAIT_PARITY_RELAXED(addr, par) do {                                    \
    uint32_t _m = (uint32_t)(addr), _p = (uint32_t)(par), _d;                           \
    asm volatile("{\n\t.reg .pred p;\n\t"                                               \
        "mbarrier.try_wait.parity.relaxed.cta.shared::cta.b64 p, [%1], %2, 0x989680;\n\t" \
        "selp.b32 %0, 1, 0, p;\n\t}" : "=r"(_d) : "r"(_m), "r"(_p) : "memory");         \
    if (!_d) {                                                                          \
        asm volatile("{\n\t.reg .pred P1;\n\t"                                          \
            "WL_%=:\n\t"                                                                \
            "mbarrier.try_wait.parity.relaxed.cta.shared::cta.b64 P1, [%0], %1, 0x989680;\n\t" \
            "@P1 bra.uni WD_%=;\n\tbra.uni WL_%=;\n\tWD_%=:\n\t}"                       \
            :: "r"(_m), "r"(_p) : "memory");                                            \
    }                                                                                   \
} while (0)

// bulk async copy global -> shared, tx-signaled on mbarrier
__device__ __forceinline__ void bulk_g2s(uint32_t dst, const void* src, uint32_t bytes, uint32_t mbar) {
    asm volatile("cp.async.bulk.shared::cluster.global.mbarrier::complete_tx::bytes [%0], [%1], %2, [%3];"
                 :: "r"(dst), "l"(src), "r"(bytes), "r"(mbar) : "memory");
}

__device__ __forceinline__ void ldsm_x4(uint32_t& r0, uint32_t& r1, uint32_t& r2, uint32_t& r3, uint32_t addr) {
    asm volatile("ldmatrix.sync.aligned.m8n8.x4.shared.b16 {%0,%1,%2,%3}, [%4];"
                 : "=r"(r0), "=r"(r1), "=r"(r2), "=r"(r3) : "r"(addr));
}

__device__ __forceinline__ void mma16816(float& c0, float& c1, float& c2, float& c3,
                                         uint32_t a0, uint32_t a1, uint32_t a2, uint32_t a3,
                                         uint32_t b0, uint32_t b1) {
    asm volatile("mma.sync.aligned.m16n8k16.row.col.f32.f16.f16.f32 "
                 "{%0,%1,%2,%3}, {%4,%5,%6,%7}, {%8,%9}, {%0,%1,%2,%3};"
                 : "+f"(c0), "+f"(c1), "+f"(c2), "+f"(c3)
                 : "r"(a0), "r"(a1), "r"(a2), "r"(a3), "r"(b0), "r"(b1));
}

// ---------------------------------------------------------------------------
// Prep 1: x f32 -> fp16, tiled + swizzled into g_A. Thread: 8 k of one row.
// ---------------------------------------------------------------------------
__global__ void __launch_bounds__(256) convert_x_kernel(const float* __restrict__ x) {
    int t = blockIdx.x * 256 + threadIdx.x;            // < 8192*512
    int m = t >> 9, c = t & 511, k0 = c << 3;
    const float4* src = reinterpret_cast<const float4*>(x + (size_t)m * 4096 + k0);
    float4 a = src[0], b = src[1];
    __half2 h[4];
    h[0] = __floats2half2_rn(a.x, a.y);
    h[1] = __floats2half2_rn(a.z, a.w);
    h[2] = __floats2half2_rn(b.x, b.y);
    h[3] = __floats2half2_rn(b.z, b.w);
    int m_blk = m >> 7, row = m & 127, ks = k0 >> 6, koff = k0 & 63;
    uint32_t off = (uint32_t)(m_blk * 64 + ks) * 16384u + swz((uint32_t)(row * 128 + koff * 2));
    *reinterpret_cast<uint4*>(reinterpret_cast<char*>(g_A) + off) = *reinterpret_cast<uint4*>(h);
}

// ---------------------------------------------------------------------------
// Prep 2: int4 -> fp16 dequant, tiled + swizzled into g_W. Thread: 8 k of one row.
// ---------------------------------------------------------------------------
__global__ void __launch_bounds__(256) dequant_w_kernel(const int* __restrict__ wp,
                                                        const float* __restrict__ scales) {
    int t = blockIdx.x * 256 + threadIdx.x;            // < 4096*512
    int o = t >> 9, c = t & 511, k0 = c << 3;
    int4 p = *reinterpret_cast<const int4*>(wp + (size_t)o * 2048 + (k0 >> 1));
    float s = __ldg(scales + o * 32 + (k0 >> 7));
    int pv[4] = {p.x, p.y, p.z, p.w};
    __half2 h[4];
#pragma unroll
    for (int i = 0; i < 4; i++) {
        float lo = (float)((pv[i] & 15) - 8) * s;
        float hi = (float)(((pv[i] >> 4) & 15) - 8) * s;
        h[i] = __floats2half2_rn(lo, hi);
    }
    int n_blk = o >> 8, row = o & 255, ks = k0 >> 6, koff = k0 & 63;
    uint32_t off = (uint32_t)(n_blk * 64 + ks) * 32768u + swz((uint32_t)(row * 128 + koff * 2));
    *reinterpret_cast<uint4*>(reinterpret_cast<char*>(g_W) + off) = *reinterpret_cast<uint4*>(h);
}

// ---------------------------------------------------------------------------
// GEMM: 128x256x(64/stage), 8 compute warps (64x64 each) + 1 producer warp
// ---------------------------------------------------------------------------
#define SMEM_FULL   0                          // 4 x 8B
#define SMEM_EMPTY  32                         // 4 x 8B
#define SMEM_A_OFF  1024
#define SMEM_B_OFF  (1024 + STAGES * 16384)    // 66560
#define SMEM_TOTAL  (SMEM_B_OFF + STAGES * 32768)  // 197632

__global__ void __launch_bounds__(288, 1)
gemm_kernel(const float* __restrict__ bias, float* __restrict__ out) {
    extern __shared__ char smem[];
    uint32_t sb = smem_u32(smem);
    int tid = threadIdx.x, wid = tid >> 5, lane = tid & 31;

    if (tid == 0) {
#pragma unroll
        for (int s = 0; s < STAGES; s++) {
            MBARRIER_INIT(sb + SMEM_FULL + s * 8, 1u);   // tx-based
            MBARRIER_INIT(sb + SMEM_EMPTY + s * 8, 8u);  // 8 compute warps
        }
    }
    __syncthreads();

    int n_tile = blockIdx.x & 15;     // n-major rasterization: W stays hot in L2
    int m_tile = blockIdx.x >> 4;

    if (wid == 8) {
        // ---------------- producer ----------------
        if (lane == 0) {
            const char* Abase = reinterpret_cast<const char*>(g_A) + (size_t)(m_tile * 64) * 16384;
            const char* Bbase = reinterpret_cast<const char*>(g_W) + (size_t)(n_tile * 64) * 32768;
            for (int it = 0; it < K_ITERS; ++it) {
                int s = it & 3, ph = 1 ^ ((it >> 2) & 1);
                MBARRIER_WAIT_PARITY_RELAXED(sb + SMEM_EMPTY + s * 8, ph);
                MBARRIER_EXPECT_TX(sb + SMEM_FULL + s * 8, 49152u);
                bulk_g2s(sb + SMEM_A_OFF + s * 16384, Abase + (size_t)it * 16384, 16384u,
                         sb + SMEM_FULL + s * 8);
                bulk_g2s(sb + SMEM_B_OFF + s * 32768, Bbase + (size_t)it * 32768, 32768u,
                         sb + SMEM_FULL + s * 8);
            }
        }
        return;
    }

    // ---------------- compute warps ----------------
    int wm = wid >> 2;      // 0..1  -> 64-row slab
    int wn = wid & 3;       // 0..3  -> 64-col slab

    float acc[4][8][4];
#pragma unroll
    for (int i = 0; i < 4; i++)
#pragma unroll
        for (int j = 0; j < 8; j++)
#pragma unroll
            for (int v = 0; v < 4; v++) acc[i][j][v] = 0.0f;

    // per-lane static pieces of ldmatrix addresses (byte offsets before swizzle)
    // A: row = wm*64 + mi*16 + (lane&15);  kcol16B = (lane>>4)
    uint32_t a_row = (uint32_t)(wm * 64 + (lane & 15));
    uint32_t a_koff = ((uint32_t)(lane >> 4)) * 16u;           // bytes
    // B: row = wn*64 + ni*16 + ((lane>>4)&1)*8 + (lane&7); kcol8 = (lane>>3)&1
    uint32_t b_row = (uint32_t)(wn * 64 + ((lane >> 4) & 1) * 8 + (lane & 7));
    uint32_t b_koff = ((uint32_t)((lane >> 3) & 1)) * 16u;     // bytes

    for (int it = 0; it < K_ITERS; ++it) {
        int s = it & 3, ph = (it >> 2) & 1;
        MBARRIER_WAIT_PARITY(sb + SMEM_FULL + s * 8, ph);
        uint32_t sA = sb + SMEM_A_OFF + (uint32_t)s * 16384u;
        uint32_t sB = sb + SMEM_B_OFF + (uint32_t)s * 32768u;

#pragma unroll
        for (int k16 = 0; k16 < 4; ++k16) {
            uint32_t a[4][4], b[4][4];
#pragma unroll
            for (int mi = 0; mi < 4; ++mi) {
                uint32_t byte = (a_row + (uint32_t)mi * 16u) * 128u + (uint32_t)k16 * 32u + a_koff;
                ldsm_x4(a[mi][0], a[mi][1], a[mi][2], a[mi][3], sA + swz(byte));
            }
#pragma unroll
            for (int ni = 0; ni < 4; ++ni) {
                uint32_t byte = (b_row + (uint32_t)ni * 16u) * 128u + (uint32_t)k16 * 32u + b_koff;
                ldsm_x4(b[ni][0], b[ni][1], b[ni][2], b[ni][3], sB + swz(byte));
            }
#pragma unroll
            for (int mi = 0; mi < 4; ++mi)
#pragma unroll
                for (int nj = 0; nj < 8; ++nj) {
                    uint32_t b0 = b[nj >> 1][(nj & 1) * 2];
                    uint32_t b1 = b[nj >> 1][(nj & 1) * 2 + 1];
                    mma16816(acc[mi][nj][0], acc[mi][nj][1], acc[mi][nj][2], acc[mi][nj][3],
                             a[mi][0], a[mi][1], a[mi][2], a[mi][3], b0, b1);
                }
        }
        __syncwarp();
        if (lane == 0) MBARRIER_ARRIVE(sb + SMEM_EMPTY + s * 8);
    }

    // ---------------- epilogue ----------------
    int row0 = m_tile * 128 + wm * 64 + (lane >> 2);
    int col0 = n_tile * 256 + wn * 64 + (lane & 3) * 2;
    float2 bb[8];
#pragma unroll
    for (int nj = 0; nj < 8; ++nj)
        bb[nj] = *reinterpret_cast<const float2*>(bias + col0 + nj * 8);
#pragma unroll
    for (int mi = 0; mi < 4; ++mi) {
        float* p0 = out + (size_t)(row0 + mi * 16) * 4096 + col0;
        float* p1 = out + (size_t)(row0 + mi * 16 + 8) * 4096 + col0;
#pragma unroll
        for (int nj = 0; nj < 8; ++nj) {
            float2 v0 = {acc[mi][nj][0] + bb[nj].x, acc[mi][nj][1] + bb[nj].y};
            float2 v1 = {acc[mi][nj][2] + bb[nj].x, acc[mi][nj][3] + bb[nj].y};
            *reinterpret_cast<float2*>(p0 + nj * 8) = v0;
            *reinterpret_cast<float2*>(p1 + nj * 8) = v1;
        }
    }
}

// ---------------------------------------------------------------------------
// kernel_launch
// inputs: 0=x f32[8192*4096], 1=weight_packed i32[4096*2048], 2=scales f32[4096*32],
//         3=zeros (unused), 4=bias f32[4096];  out f32[8192*4096]
// ---------------------------------------------------------------------------
extern "C" void kernel_launch(void* const* d_in, const int* in_sizes, int n_in,
                              void* d_out, int out_size) {
    (void)in_sizes; (void)n_in; (void)out_size;
    const float* x      = (const float*)d_in[0];
    const int*   wp     = (const int*)d_in[1];
    const float* scales = (const float*)d_in[2];
    const float* bias   = (const float*)d_in[4];
    float* out = (float*)d_out;

    convert_x_kernel<<<16384, 256>>>(x);
    dequant_w_kernel<<<8192, 256>>>(wp, scales);

    cudaFuncSetAttribute(gemm_kernel, cudaFuncAttributeMaxDynamicSharedMemorySize, SMEM_TOTAL);
    gemm_kernel<<<1024, 288, SMEM_TOTAL>>>(bias, out);
}

// round 6
// speedup vs baseline: 1.0090x; 1.0090x over previous
#include <cuda_runtime.h>
#include <cuda_fp16.h>
#include <cstdint>

// ============================================================================
// QuantizedLinear: out[8192,4096] = x[8192,4096] @ dequant(W4)[4096,4096]^T + bias
// mma.sync fp16 GEMM (compute_103-safe: no tcgen05 / no "a" features).
// Operands pre-converted + pre-tiled + SW128-pre-swizzled into __device__ scratch,
// streamed into smem with cp.async.bulk + mbarrier pipeline, read via ldmatrix.
// ============================================================================

#define M_TOTAL   8192
#define N_TOTAL   4096
#define K_TOTAL   4096
#define BK        64            // k per stage (64 halves = 128B rows)
#define STAGES    4
#define K_ITERS   (K_TOTAL / BK)   // 64

// g_A: [m_blk(64)][k_stage(64)] blocks of 128x64 fp16 (16KB), SW128-swizzled
// g_W: [n_blk(16)][k_stage(64)] blocks of 256x64 fp16 (32KB), SW128-swizzled
__device__ __align__(1024) __half g_A[33554432];  // 64 MiB
__device__ __align__(1024) __half g_W[16777216];  // 32 MiB

__device__ __forceinline__ uint32_t swz(uint32_t x) { return x ^ ((x >> 3) & 0x70); }

__device__ __forceinline__ uint32_t smem_u32(const void* p) {
    uint32_t a;
    asm("{ .reg .u64 t; cvta.to.shared.u64 t, %1; cvt.u32.u64 %0, t; }" : "=r"(a) : "l"(p));
    return a;
}

#define MBARRIER_INIT(addr, cnt) \
    asm volatile("mbarrier.init.shared.b64 [%0], %1;" :: "r"((uint32_t)(addr)), "r"((uint32_t)(cnt)) : "memory")

#define MBARRIER_EXPECT_TX(addr, bytes) \
    asm volatile("mbarrier.arrive.expect_tx.shared.b64 _, [%0], %1;" :: "r"((uint32_t)(addr)), "r"((uint32_t)(bytes)) : "memory")

#define MBARRIER_ARRIVE(addr) \
    asm volatile("mbarrier.arrive.shared.b64 _, [%0];" :: "r"((uint32_t)(addr)) : "memory")

#define MBARRIER_WAIT_PARITY(addr, par) do {                                            \
    uint32_t _m = (uint32_t)(addr), _p = (uint32_t)(par), _d;                           \
    asm volatile("{\n\t.reg .pred p;\n\t"                                               \
        "mbarrier.try_wait.parity.acquire.cta.shared::cta.b64 p, [%1], %2;\n\t"         \
        "selp.b32 %0, 1, 0, p;\n\t}" : "=r"(_d) : "r"(_m), "r"(_p) : "memory");         \
    if (!_d) {                                                                          \
        asm volatile("{\n\t.reg .pred P1;\n\t"                                          \
            "WL_%=:\n\t"                                                                \
            "mbarrier.try_wait.parity.acquire.cta.shared::cta.b64 P1, [%0], %1, 0x989680;\n\t" \
            "@P1 bra.uni WD_%=;\n\tbra.uni WL_%=;\n\tWD_%=:\n\t}"                       \
            :: "r"(_m), "r"(_p) : "memory");                                            \
    }                                                                                   \
} while (0)

#define MBARRIER_WAIT_PARITY_RELAXED(addr, par) do {                                    \
    uint32_t _m = (uint32_t)(addr), _p = (uint32_t)(par), _d;                           \
    asm volatile("{\n\t.reg .pred p;\n\t"                                               \
        "mbarrier.try_wait.parity.relaxed.cta.shared::cta.b64 p, [%1], %2, 0x989680;\n\t" \
        "selp.b32 %0, 1, 0, p;\n\t}" : "=r"(_d) : "r"(_m), "r"(_p) : "memory");         \
    if (!_d) {                                                                          \
        asm volatile("{\n\t.reg .pred P1;\n\t"                                          \
            "WL_%=:\n\t"                                                                \
            "mbarrier.try_wait.parity.relaxed.cta.shared::cta.b64 P1, [%0], %1, 0x989680;\n\t" \
            "@P1 bra.uni WD_%=;\n\tbra.uni WL_%=;\n\tWD_%=:\n\t}"                       \
            :: "r"(_m), "r"(_p) : "memory");                                            \
    }                                                                                   \
} while (0)

// bulk async copy global -> shared, tx-signaled on mbarrier
__device__ __forceinline__ void bulk_g2s(uint32_t dst, const void* src, uint32_t bytes, uint32_t mbar) {
    asm volatile("cp.async.bulk.shared::cluster.global.mbarrier::complete_tx::bytes [%0], [%1], %2, [%3];"
                 :: "r"(dst), "l"(src), "r"(bytes), "r"(mbar) : "memory");
}

__device__ __forceinline__ void ldsm_x4(uint32_t& r0, uint32_t& r1, uint32_t& r2, uint32_t& r3, uint32_t addr) {
    asm volatile("ldmatrix.sync.aligned.m8n8.x4.shared.b16 {%0,%1,%2,%3}, [%4];"
                 : "=r"(r0), "=r"(r1), "=r"(r2), "=r"(r3) : "r"(addr));
}

__device__ __forceinline__ void mma16816(float& c0, float& c1, float& c2, float& c3,
                                         uint32_t a0, uint32_t a1, uint32_t a2, uint32_t a3,
                                         uint32_t b0, uint32_t b1) {
    asm volatile("mma.sync.aligned.m16n8k16.row.col.f32.f16.f16.f32 "
                 "{%0,%1,%2,%3}, {%4,%5,%6,%7}, {%8,%9}, {%0,%1,%2,%3};"
                 : "+f"(c0), "+f"(c1), "+f"(c2), "+f"(c3)
                 : "r"(a0), "r"(a1), "r"(a2), "r"(a3), "r"(b0), "r"(b1));
}

// ---------------------------------------------------------------------------
// Prep 1: x f32 -> fp16, tiled + swizzled into g_A. Thread: 8 k of one row.
// ---------------------------------------------------------------------------
__global__ void __launch_bounds__(256) convert_x_kernel(const float* __restrict__ x) {
    int t = blockIdx.x * 256 + threadIdx.x;            // < 8192*512
    int m = t >> 9, c = t & 511, k0 = c << 3;
    const float4* src = reinterpret_cast<const float4*>(x + (size_t)m * 4096 + k0);
    float4 a = src[0], b = src[1];
    __half2 h[4];
    h[0] = __floats2half2_rn(a.x, a.y);
    h[1] = __floats2half2_rn(a.z, a.w);
    h[2] = __floats2half2_rn(b.x, b.y);
    h[3] = __floats2half2_rn(b.z, b.w);
    int m_blk = m >> 7, row = m & 127, ks = k0 >> 6, koff = k0 & 63;
    uint32_t off = (uint32_t)(m_blk * 64 + ks) * 16384u + swz((uint32_t)(row * 128 + koff * 2));
    *reinterpret_cast<uint4*>(reinterpret_cast<char*>(g_A) + off) = *reinterpret_cast<uint4*>(h);
}

// ---------------------------------------------------------------------------
// Prep 2: int4 -> fp16 dequant, tiled + swizzled into g_W. Thread: 8 k of one row.
// ---------------------------------------------------------------------------
__global__ void __launch_bounds__(256) dequant_w_kernel(const int* __restrict__ wp,
                                                        const float* __restrict__ scales) {
    int t = blockIdx.x * 256 + threadIdx.x;            // < 4096*512
    int o = t >> 9, c = t & 511, k0 = c << 3;
    int4 p = *reinterpret_cast<const int4*>(wp + (size_t)o * 2048 + (k0 >> 1));
    float s = __ldg(scales + o * 32 + (k0 >> 7));
    int pv[4] = {p.x, p.y, p.z, p.w};
    __half2 h[4];
#pragma unroll
    for (int i = 0; i < 4; i++) {
        float lo = (float)((pv[i] & 15) - 8) * s;
        float hi = (float)(((pv[i] >> 4) & 15) - 8) * s;
        h[i] = __floats2half2_rn(lo, hi);
    }
    int n_blk = o >> 8, row = o & 255, ks = k0 >> 6, koff = k0 & 63;
    uint32_t off = (uint32_t)(n_blk * 64 + ks) * 32768u + swz((uint32_t)(row * 128 + koff * 2));
    *reinterpret_cast<uint4*>(reinterpret_cast<char*>(g_W) + off) = *reinterpret_cast<uint4*>(h);
}

// ---------------------------------------------------------------------------
// GEMM: 128x256x(64/stage), 8 compute warps (64x64 each) + 1 producer warp
// ---------------------------------------------------------------------------
#define SMEM_FULL   0                          // 4 x 8B
#define SMEM_EMPTY  32                         // 4 x 8B
#define SMEM_A_OFF  1024
#define SMEM_B_OFF  (1024 + STAGES * 16384)    // 66560
#define SMEM_TOTAL  (SMEM_B_OFF + STAGES * 32768)  // 197632

__global__ void __launch_bounds__(288, 1)
gemm_kernel(const float* __restrict__ bias, float* __restrict__ out) {
    extern __shared__ char smem[];
    uint32_t sb = smem_u32(smem);
    int tid = threadIdx.x, wid = tid >> 5, lane = tid & 31;

    if (tid == 0) {
#pragma unroll
        for (int s = 0; s < STAGES; s++) {
            MBARRIER_INIT(sb + SMEM_FULL + s * 8, 1u);   // tx-based
            MBARRIER_INIT(sb + SMEM_EMPTY + s * 8, 8u);  // 8 compute warps
        }
    }
    __syncthreads();

    int n_tile = blockIdx.x & 15;     // n-major rasterization: W stays hot in L2
    int m_tile = blockIdx.x >> 4;

    if (wid == 8) {
        // ---------------- producer ----------------
        if (lane == 0) {
            const char* Abase = reinterpret_cast<const char*>(g_A) + (size_t)(m_tile * 64) * 16384;
            const char* Bbase = reinterpret_cast<const char*>(g_W) + (size_t)(n_tile * 64) * 32768;
            for (int it = 0; it < K_ITERS; ++it) {
                int s = it & 3, ph = 1 ^ ((it >> 2) & 1);
                MBARRIER_WAIT_PARITY_RELAXED(sb + SMEM_EMPTY + s * 8, ph);
                MBARRIER_EXPECT_TX(sb + SMEM_FULL + s * 8, 49152u);
                bulk_g2s(sb + SMEM_A_OFF + s * 16384, Abase + (size_t)it * 16384, 16384u,
                         sb + SMEM_FULL + s * 8);
                bulk_g2s(sb + SMEM_B_OFF + s * 32768, Bbase + (size_t)it * 32768, 32768u,
                         sb + SMEM_FULL + s * 8);
            }
        }
        return;
    }

    // ---------------- compute warps ----------------
    int wm = wid >> 2;      // 0..1  -> 64-row slab
    int wn = wid & 3;       // 0..3  -> 64-col slab

    float acc[4][8][4];
#pragma unroll
    for (int i = 0; i < 4; i++)
#pragma unroll
        for (int j = 0; j < 8; j++)
#pragma unroll
            for (int v = 0; v < 4; v++) acc[i][j][v] = 0.0f;

    // per-lane static pieces of ldmatrix addresses (byte offsets before swizzle)
    // A: row = wm*64 + mi*16 + (lane&15);  kcol16B = (lane>>4)
    uint32_t a_row = (uint32_t)(wm * 64 + (lane & 15));
    uint32_t a_koff = ((uint32_t)(lane >> 4)) * 16u;           // bytes
    // B: row = wn*64 + ni*16 + ((lane>>4)&1)*8 + (lane&7); kcol8 = (lane>>3)&1
    uint32_t b_row = (uint32_t)(wn * 64 + ((lane >> 4) & 1) * 8 + (lane & 7));
    uint32_t b_koff = ((uint32_t)((lane >> 3) & 1)) * 16u;     // bytes

    for (int it = 0; it < K_ITERS; ++it) {
        int s = it & 3, ph = (it >> 2) & 1;
        MBARRIER_WAIT_PARITY(sb + SMEM_FULL + s * 8, ph);
        uint32_t sA = sb + SMEM_A_OFF + (uint32_t)s * 16384u;
        uint32_t sB = sb + SMEM_B_OFF + (uint32_t)s * 32768u;

        // k16 = 0..2: load fragments + MMA
#pragma unroll
        for (int k16 = 0; k16 < 3; ++k16) {
            uint32_t a[4][4], b[4][4];
#pragma unroll
            for (int mi = 0; mi < 4; ++mi) {
                uint32_t byte = (a_row + (uint32_t)mi * 16u) * 128u + (uint32_t)k16 * 32u + a_koff;
                ldsm_x4(a[mi][0], a[mi][1], a[mi][2], a[mi][3], sA + swz(byte));
            }
#pragma unroll
            for (int ni = 0; ni < 4; ++ni) {
                uint32_t byte = (b_row + (uint32_t)ni * 16u) * 128u + (uint32_t)k16 * 32u + b_koff;
                ldsm_x4(b[ni][0], b[ni][1], b[ni][2], b[ni][3], sB + swz(byte));
            }
#pragma unroll
            for (int mi = 0; mi < 4; ++mi)
#pragma unroll
                for (int nj = 0; nj < 8; ++nj) {
                    uint32_t b0 = b[nj >> 1][(nj & 1) * 2];
                    uint32_t b1 = b[nj >> 1][(nj & 1) * 2 + 1];
                    mma16816(acc[mi][nj][0], acc[mi][nj][1], acc[mi][nj][2], acc[mi][nj][3],
                             a[mi][0], a[mi][1], a[mi][2], a[mi][3], b0, b1);
                }
        }

        // k16 = 3: load fragments, RELEASE the stage early (arrive has release
        // semantics ordering prior ldmatrix reads), then run the MMAs.
        {
            uint32_t a[4][4], b[4][4];
#pragma unroll
            for (int mi = 0; mi < 4; ++mi) {
                uint32_t byte = (a_row + (uint32_t)mi * 16u) * 128u + 96u + a_koff;
                ldsm_x4(a[mi][0], a[mi][1], a[mi][2], a[mi][3], sA + swz(byte));
            }
#pragma unroll
            for (int ni = 0; ni < 4; ++ni) {
                uint32_t byte = (b_row + (uint32_t)ni * 16u) * 128u + 96u + b_koff;
                ldsm_x4(b[ni][0], b[ni][1], b[ni][2], b[ni][3], sB + swz(byte));
            }
            if (lane == 0) MBARRIER_ARRIVE(sb + SMEM_EMPTY + s * 8);
#pragma unroll
            for (int mi = 0; mi < 4; ++mi)
#pragma unroll
                for (int nj = 0; nj < 8; ++nj) {
                    uint32_t b0 = b[nj >> 1][(nj & 1) * 2];
                    uint32_t b1 = b[nj >> 1][(nj & 1) * 2 + 1];
                    mma16816(acc[mi][nj][0], acc[mi][nj][1], acc[mi][nj][2], acc[mi][nj][3],
                             a[mi][0], a[mi][1], a[mi][2], a[mi][3], b0, b1);
                }
        }
    }

    // ---------------- epilogue ----------------
    int row0 = m_tile * 128 + wm * 64 + (lane >> 2);
    int col0 = n_tile * 256 + wn * 64 + (lane & 3) * 2;
    float2 bb[8];
#pragma unroll
    for (int nj = 0; nj < 8; ++nj)
        bb[nj] = *reinterpret_cast<const float2*>(bias + col0 + nj * 8);
#pragma unroll
    for (int mi = 0; mi < 4; ++mi) {
        float* p0 = out + (size_t)(row0 + mi * 16) * 4096 + col0;
        float* p1 = out + (size_t)(row0 + mi * 16 + 8) * 4096 + col0;
#pragma unroll
        for (int nj = 0; nj < 8; ++nj) {
            float2 v0 = {acc[mi][nj][0] + bb[nj].x, acc[mi][nj][1] + bb[nj].y};
            float2 v1 = {acc[mi][nj][2] + bb[nj].x, acc[mi][nj][3] + bb[nj].y};
            *reinterpret_cast<float2*>(p0 + nj * 8) = v0;
            *reinterpret_cast<float2*>(p1 + nj * 8) = v1;
        }
    }
}

// ---------------------------------------------------------------------------
// kernel_launch
// inputs: 0=x f32[8192*4096], 1=weight_packed i32[4096*2048], 2=scales f32[4096*32],
//         3=zeros (unused), 4=bias f32[4096];  out f32[8192*4096]
// ---------------------------------------------------------------------------
extern "C" void kernel_launch(void* const* d_in, const int* in_sizes, int n_in,
                              void* d_out, int out_size) {
    (void)in_sizes; (void)n_in; (void)out_size;
    const float* x      = (const float*)d_in[0];
    const int*   wp     = (const int*)d_in[1];
    const float* scales = (const float*)d_in[2];
    const float* bias   = (const float*)d_in[4];
    float* out = (float*)d_out;

    convert_x_kernel<<<16384, 256>>>(x);
    dequant_w_kernel<<<8192, 256>>>(wp, scales);

    cudaFuncSetAttribute(gemm_kernel, cudaFuncAttributeMaxDynamicSharedMemorySize, SMEM_TOTAL);
    gemm_kernel<<<1024, 288, SMEM_TOTAL>>>(bias, out);
}